// round 4
// baseline (speedup 1.0000x reference)
#include <cuda_runtime.h>
#include <cstdint>

#define BATCH 64
#define TLEN 160
#define HID 256
#define MAXLEN 2000

// Block = (frame-tile, batch, which-output). 512 threads = 16 warps = 16 frames.
// z==0 blocks gather x rows -> out; z==1 blocks gather penc rows -> pos.
// Each block writes ONE contiguous 16KB stream (single DRAM stream per block).
__global__ __launch_bounds__(512) void lr_fused_kernel(
    const float* __restrict__ x,
    const float* __restrict__ penc,
    const int*   __restrict__ dur,
    float* __restrict__ out,
    float* __restrict__ pos,
    float* __restrict__ mel_out)
{
    __shared__ int s_csum[TLEN];
    __shared__ int s_tot[TLEN / 32];

    const int b    = blockIdx.y;
    const int z    = blockIdx.z;
    const int tid  = threadIdx.x;
    const int lane = tid & 31;
    const int warp = tid >> 5;

    // ---- in-block inclusive scan of duration[b, :] (warps 0..4) ----
    int v = 0;
    if (tid < TLEN) {
        v = dur[b * TLEN + tid];
#pragma unroll
        for (int off = 1; off < 32; off <<= 1) {
            int n = __shfl_up_sync(0xffffffffu, v, off);
            if (lane >= off) v += n;
        }
        if (lane == 31) s_tot[warp] = v;
    }
    __syncthreads();
    if (tid < TLEN) {
        int add = 0;
#pragma unroll
        for (int i = 0; i < TLEN / 32; ++i)
            if (i < warp) add += s_tot[i];
        s_csum[tid] = v + add;
    }
    __syncthreads();

    const int mel = s_csum[TLEN - 1];
    if (z == 0 && blockIdx.x == 0 && tid == 0) mel_out[b] = (float)mel;

    // ---- one warp per frame: 16 frames per block ----
    const int f = blockIdx.x * 16 + warp;
    const bool valid = (f < mel);

    float4 v0, v1;
    if (valid) {
        // searchsorted(csum, f, side='right'): first idx with csum[idx] > f
        int lo = 0, hi = TLEN;
#pragma unroll 8
        while (lo < hi) {
            int mid = (lo + hi) >> 1;
            if (s_csum[mid] <= f) lo = mid + 1; else hi = mid;
        }
        int idx  = lo < (TLEN - 1) ? lo : (TLEN - 1);
        int excl = idx ? s_csum[idx - 1] : 0;
        int pw   = f - excl;

        const float4* src = (z == 0)
            ? (const float4*)(x + ((size_t)b * TLEN + idx) * HID)
            : (const float4*)(penc + (size_t)pw * HID);
        v0 = src[lane];
        v1 = src[lane + 32];
    } else {
        v0 = v1 = make_float4(0.f, 0.f, 0.f, 0.f);
    }

    float* dstbase = (z == 0) ? out : pos;
    float4* dst = (float4*)(dstbase + ((size_t)b * MAXLEN + f) * HID);
    __stcs(dst + lane, v0);
    __stcs(dst + lane + 32, v1);
}

extern "C" void kernel_launch(void* const* d_in, const int* in_sizes, int n_in,
                              void* d_out, int out_size) {
    const float* x    = (const float*)d_in[0];   // (64,160,256) f32
    const float* penc = (const float*)d_in[1];   // (2001,256) f32
    const int*   dur  = (const int*)d_in[2];     // (64,160) int32
    // d_in[3] (max_len scalar) unused — fixed at 2000

    float* out = (float*)d_out;                                   // (64,2000,256)
    float* pos = out + (size_t)BATCH * MAXLEN * HID;              // (64,2000,256)
    float* mel = out + 2 * (size_t)BATCH * MAXLEN * HID;          // (64,)

    dim3 grid(MAXLEN / 16, BATCH, 2);
    lr_fused_kernel<<<grid, 512>>>(x, penc, dur, out, pos, mel);
}

// round 5
// speedup vs baseline: 1.0539x; 1.0539x over previous
#include <cuda_runtime.h>
#include <cstdint>

#define BATCH 64
#define TLEN 160
#define HID 256
#define MAXLEN 2000

// Fused kernel (R2 structure): one block = 8 output frames of one batch.
// Scan duration[b,:] in-block, one warp per frame, binary search, then
// 2 x 1KB row copies with DEFAULT-policy stores (dirty lines recycle in L2
// across graph replays -> less DRAM writeback per replay).
__global__ __launch_bounds__(256) void lr_fused_kernel(
    const float* __restrict__ x,
    const float* __restrict__ penc,
    const int*   __restrict__ dur,
    float* __restrict__ out,
    float* __restrict__ pos,
    float* __restrict__ mel_out)
{
    __shared__ int s_csum[TLEN];
    __shared__ int s_tot[TLEN / 32];

    const int b    = blockIdx.y;
    const int tid  = threadIdx.x;
    const int lane = tid & 31;
    const int warp = tid >> 5;

    // ---- in-block inclusive scan of duration[b, :] ----
    int v = 0;
    if (tid < TLEN) {
        v = dur[b * TLEN + tid];
#pragma unroll
        for (int off = 1; off < 32; off <<= 1) {
            int n = __shfl_up_sync(0xffffffffu, v, off);
            if (lane >= off) v += n;
        }
        if (lane == 31) s_tot[warp] = v;
    }
    __syncthreads();
    if (tid < TLEN) {
        int add = 0;
#pragma unroll
        for (int i = 0; i < TLEN / 32; ++i)
            if (i < warp) add += s_tot[i];
        s_csum[tid] = v + add;
    }
    __syncthreads();

    const int mel = s_csum[TLEN - 1];
    if (blockIdx.x == 0 && tid == 0) mel_out[b] = (float)mel;

    // ---- one warp per output frame ----
    const int f = blockIdx.x * 8 + warp;
    const bool valid = (f < mel);

    float4 o0, o1, p0, p1;
    if (valid) {
        // searchsorted(csum, f, side='right'): first idx with csum[idx] > f
        int lo = 0, hi = TLEN;
#pragma unroll 8
        while (lo < hi) {
            int mid = (lo + hi) >> 1;
            if (s_csum[mid] <= f) lo = mid + 1; else hi = mid;
        }
        int idx  = lo < (TLEN - 1) ? lo : (TLEN - 1);
        int excl = idx ? s_csum[idx - 1] : 0;
        int pw   = f - excl;

        const float4* xr = (const float4*)(x + ((size_t)b * TLEN + idx) * HID);
        const float4* pr = (const float4*)(penc + (size_t)pw * HID);
        o0 = xr[lane];  o1 = xr[lane + 32];
        p0 = pr[lane];  p1 = pr[lane + 32];
    } else {
        o0 = o1 = p0 = p1 = make_float4(0.f, 0.f, 0.f, 0.f);
    }

    const size_t row = ((size_t)b * MAXLEN + f) * HID;
    float4* ow  = (float4*)(out + row);
    float4* pw4 = (float4*)(pos + row);
    ow[lane]       = o0;
    ow[lane + 32]  = o1;
    pw4[lane]      = p0;
    pw4[lane + 32] = p1;
}

extern "C" void kernel_launch(void* const* d_in, const int* in_sizes, int n_in,
                              void* d_out, int out_size) {
    const float* x    = (const float*)d_in[0];   // (64,160,256) f32
    const float* penc = (const float*)d_in[1];   // (2001,256) f32
    const int*   dur  = (const int*)d_in[2];     // (64,160) int32
    // d_in[3] (max_len scalar) unused — fixed at 2000

    float* out = (float*)d_out;                                   // (64,2000,256)
    float* pos = out + (size_t)BATCH * MAXLEN * HID;              // (64,2000,256)
    float* mel = out + 2 * (size_t)BATCH * MAXLEN * HID;          // (64,)

    dim3 grid(MAXLEN / 8, BATCH);
    lr_fused_kernel<<<grid, 256>>>(x, penc, dur, out, pos, mel);
}

// round 7
// speedup vs baseline: 1.0934x; 1.0375x over previous
#include <cuda_runtime.h>
#include <cstdint>

#define BATCH 64
#define TLEN 160
#define HID 256
#define MAXLEN 2000

// R2 geometry: one block = 8 output frames of one batch, 256 threads.
// Scan duration[b,:] in-block; each thread t owns interval [csum-d, csum) and
// SCATTERS (idx=t, pos_within) into an 8-entry smem table for frames landing
// in this block's window. Consumer warps do 2 independent LDS instead of an
// 8-deep dependent binary search.
__global__ __launch_bounds__(256) void lr_fused_kernel(
    const float* __restrict__ x,
    const float* __restrict__ penc,
    const int*   __restrict__ dur,
    float* __restrict__ out,
    float* __restrict__ pos,
    float* __restrict__ mel_out)
{
    __shared__ int s_tot[TLEN / 32];
    __shared__ int s_idx[8];
    __shared__ int s_pw[8];
    __shared__ int s_mel;

    const int b    = blockIdx.y;
    const int base = blockIdx.x * 8;
    const int tid  = threadIdx.x;
    const int lane = tid & 31;
    const int warp = tid >> 5;

    // defaults for frames beyond mel (don't-care values, zeroed output anyway)
    if (tid < 8) { s_idx[tid] = 0; s_pw[tid] = 0; }

    // ---- warp-scan of duration[b,:] (full warps 0..4 = threads 0..159) ----
    int d = 0, v = 0;
    if (tid < TLEN) {
        d = __ldg(&dur[b * TLEN + tid]);   // keep raw duration
        v = d;
#pragma unroll
        for (int off = 1; off < 32; off <<= 1) {
            int n = __shfl_up_sync(0xffffffffu, v, off);
            if (lane >= off) v += n;
        }
        if (lane == 31) s_tot[warp] = v;
    }
    __syncthreads();

    if (tid < TLEN) {
        int add = 0;
#pragma unroll
        for (int i = 0; i < TLEN / 32; ++i)
            if (i < warp) add += s_tot[i];
        const int csum = v + add;          // inclusive cumsum at t
        const int excl = csum - d;         // exclusive cumsum at t

        if (tid == TLEN - 1) s_mel = csum;

        // scatter this thread's frames that fall in [base, base+8)
        int lo = excl > base ? excl : base;
        int hi = csum < base + 8 ? csum : base + 8;
        for (int f = lo; f < hi; ++f) {
            s_idx[f - base] = tid;
            s_pw[f - base]  = f - excl;
        }
    }
    __syncthreads();

    const int mel = s_mel;
    if (base == 0 && tid == 0) mel_out[b] = (float)mel;

    // ---- one warp per output frame ----
    const int f = base + warp;
    const bool valid = (f < mel);

    float4 o0, o1, p0, p1;
    if (valid) {
        const int idx = s_idx[warp];
        const int pw  = s_pw[warp];
        const float4* xr = (const float4*)(x + ((size_t)b * TLEN + idx) * HID);
        const float4* pr = (const float4*)(penc + (size_t)pw * HID);
        o0 = xr[lane];  o1 = xr[lane + 32];
        p0 = pr[lane];  p1 = pr[lane + 32];
    } else {
        o0 = o1 = p0 = p1 = make_float4(0.f, 0.f, 0.f, 0.f);
    }

    const size_t row = ((size_t)b * MAXLEN + f) * HID;
    float4* ow  = (float4*)(out + row);
    float4* pw4 = (float4*)(pos + row);
    __stcs(ow + lane, o0);
    __stcs(ow + lane + 32, o1);
    __stcs(pw4 + lane, p0);
    __stcs(pw4 + lane + 32, p1);
}

extern "C" void kernel_launch(void* const* d_in, const int* in_sizes, int n_in,
                              void* d_out, int out_size) {
    const float* x    = (const float*)d_in[0];   // (64,160,256) f32
    const float* penc = (const float*)d_in[1];   // (2001,256) f32
    const int*   dur  = (const int*)d_in[2];     // (64,160) int32
    // d_in[3] (max_len scalar) unused — fixed at 2000

    float* out = (float*)d_out;                                   // (64,2000,256)
    float* pos = out + (size_t)BATCH * MAXLEN * HID;              // (64,2000,256)
    float* mel = out + 2 * (size_t)BATCH * MAXLEN * HID;          // (64,)

    dim3 grid(MAXLEN / 8, BATCH);
    lr_fused_kernel<<<grid, 256>>>(x, penc, dur, out, pos, mel);
}

// round 8
// speedup vs baseline: 1.1536x; 1.0551x over previous
#include <cuda_runtime.h>
#include <cstdint>

#define BATCH 64
#define TLEN 160
#define HID 256
#define MAXLEN 2000

// per-frame decode table: e = (idx<<12)|pos_within, or -1 if frame invalid
__device__ int g_tab[BATCH * MAXLEN];

// Kernel A: per-batch scan + scatter of decode table. 64 blocks x 256 threads.
__global__ __launch_bounds__(256) void lr_prep_kernel(
    const int* __restrict__ dur, float* __restrict__ mel_out)
{
    __shared__ int s_tot[TLEN / 32];
    const int b    = blockIdx.x;
    const int tid  = threadIdx.x;
    const int lane = tid & 31;
    const int warp = tid >> 5;

    // fill table with -1 (invalid) — coalesced
    for (int f = tid; f < MAXLEN; f += 256)
        g_tab[b * MAXLEN + f] = -1;

    // scan duration[b,:]
    int d = 0, v = 0;
    if (tid < TLEN) {
        d = __ldg(&dur[b * TLEN + tid]);
        v = d;
#pragma unroll
        for (int off = 1; off < 32; off <<= 1) {
            int n = __shfl_up_sync(0xffffffffu, v, off);
            if (lane >= off) v += n;
        }
        if (lane == 31) s_tot[warp] = v;
    }
    __syncthreads();
    if (tid < TLEN) {
        int add = 0;
#pragma unroll
        for (int i = 0; i < TLEN / 32; ++i)
            if (i < warp) add += s_tot[i];
        const int csum = v + add;
        const int excl = csum - d;
        if (tid == TLEN - 1) mel_out[b] = (float)csum;

        const int hi = csum < MAXLEN ? csum : MAXLEN;
        for (int f = excl; f < hi; ++f)
            g_tab[b * MAXLEN + f] = (tid << 12) | (f - excl);
    }
}

// Kernel B: one warp per frame, no smem/barriers/search.
// Broadcast 4B table load -> decode -> 4 gather LDG.128 -> 4 streaming STG.128.
__global__ __launch_bounds__(256) void lr_copy_kernel(
    const float* __restrict__ x,
    const float* __restrict__ penc,
    float* __restrict__ out,
    float* __restrict__ pos)
{
    const int b    = blockIdx.y;
    const int tid  = threadIdx.x;
    const int lane = tid & 31;
    const int warp = tid >> 5;
    const int f    = blockIdx.x * 8 + warp;

    const int e = __ldg(&g_tab[b * MAXLEN + f]);

    float4 o0, o1, p0, p1;
    if (e >= 0) {
        const int idx = e >> 12;
        const int pw  = e & 4095;
        const float4* xr = (const float4*)(x + ((size_t)b * TLEN + idx) * HID);
        const float4* pr = (const float4*)(penc + (size_t)pw * HID);
        o0 = xr[lane];  o1 = xr[lane + 32];
        p0 = pr[lane];  p1 = pr[lane + 32];
    } else {
        o0 = o1 = p0 = p1 = make_float4(0.f, 0.f, 0.f, 0.f);
    }

    const size_t row = ((size_t)b * MAXLEN + f) * HID;
    float4* ow  = (float4*)(out + row);
    float4* pw4 = (float4*)(pos + row);
    __stcs(ow + lane, o0);
    __stcs(ow + lane + 32, o1);
    __stcs(pw4 + lane, p0);
    __stcs(pw4 + lane + 32, p1);
}

extern "C" void kernel_launch(void* const* d_in, const int* in_sizes, int n_in,
                              void* d_out, int out_size) {
    const float* x    = (const float*)d_in[0];   // (64,160,256) f32
    const float* penc = (const float*)d_in[1];   // (2001,256) f32
    const int*   dur  = (const int*)d_in[2];     // (64,160) int32
    // d_in[3] (max_len scalar) unused — fixed at 2000

    float* out = (float*)d_out;                                   // (64,2000,256)
    float* pos = out + (size_t)BATCH * MAXLEN * HID;              // (64,2000,256)
    float* mel = out + 2 * (size_t)BATCH * MAXLEN * HID;          // (64,)

    lr_prep_kernel<<<BATCH, 256>>>(dur, mel);
    dim3 grid(MAXLEN / 8, BATCH);
    lr_copy_kernel<<<grid, 256>>>(x, penc, out, pos);
}

// round 9
// speedup vs baseline: 1.1599x; 1.0055x over previous
#include <cuda_runtime.h>
#include <cstdint>

#define BATCH 64
#define TLEN 160
#define HID 256
#define MAXLEN 2000

// One fused kernel: block = 16 frames of one batch (2 per warp), 256 threads.
// In-block scan of duration[b,:], one binary search per frame, then both
// frames' 8 gather loads issued back-to-back (8-deep MLP) before 8 streaming
// stores. grid = (125, 64) = 8000 blocks -> half the scans of R2.
__global__ __launch_bounds__(256) void lr_fused_kernel(
    const float* __restrict__ x,
    const float* __restrict__ penc,
    const int*   __restrict__ dur,
    float* __restrict__ out,
    float* __restrict__ pos,
    float* __restrict__ mel_out)
{
    __shared__ int s_csum[TLEN];
    __shared__ int s_tot[TLEN / 32];

    const int b    = blockIdx.y;
    const int tid  = threadIdx.x;
    const int lane = tid & 31;
    const int warp = tid >> 5;

    // ---- in-block inclusive scan of duration[b, :] ----
    int v = 0;
    if (tid < TLEN) {
        v = __ldg(&dur[b * TLEN + tid]);
#pragma unroll
        for (int off = 1; off < 32; off <<= 1) {
            int n = __shfl_up_sync(0xffffffffu, v, off);
            if (lane >= off) v += n;
        }
        if (lane == 31) s_tot[warp] = v;
    }
    __syncthreads();
    if (tid < TLEN) {
        int add = 0;
#pragma unroll
        for (int i = 0; i < TLEN / 32; ++i)
            if (i < warp) add += s_tot[i];
        s_csum[tid] = v + add;
    }
    __syncthreads();

    const int mel = s_csum[TLEN - 1];
    if (blockIdx.x == 0 && tid == 0) mel_out[b] = (float)mel;

    // ---- two frames per warp: f0 = base+warp, f1 = f0+8 ----
    const int fbase = blockIdx.x * 16;

    float4 a0, a1, q0, q1;   // frame 0: out row pair + pos row pair
    float4 c0, c1, r0, r1;   // frame 1
    int f[2]; f[0] = fbase + warp; f[1] = fbase + warp + 8;

    float4* dst_o[2]; float4* dst_p[2];

#pragma unroll
    for (int k = 0; k < 2; ++k) {
        const size_t row = ((size_t)b * MAXLEN + f[k]) * HID;
        dst_o[k] = (float4*)(out + row);
        dst_p[k] = (float4*)(pos + row);
    }

    // searches (cheap, smem) for both frames
    int idx[2], pw[2]; bool val[2];
#pragma unroll
    for (int k = 0; k < 2; ++k) {
        val[k] = f[k] < mel;
        int lo = 0, hi = TLEN;
        while (lo < hi) {
            int mid = (lo + hi) >> 1;
            if (s_csum[mid] <= f[k]) lo = mid + 1; else hi = mid;
        }
        idx[k] = lo < (TLEN - 1) ? lo : (TLEN - 1);
        int excl = idx[k] ? s_csum[idx[k] - 1] : 0;
        pw[k] = f[k] - excl;
    }

    // issue all 8 gather loads back-to-back (max MLP), then all stores
    const float4 z = make_float4(0.f, 0.f, 0.f, 0.f);
    const float4* xr0 = (const float4*)(x + ((size_t)b * TLEN + idx[0]) * HID);
    const float4* pr0 = (const float4*)(penc + (size_t)pw[0] * HID);
    const float4* xr1 = (const float4*)(x + ((size_t)b * TLEN + idx[1]) * HID);
    const float4* pr1 = (const float4*)(penc + (size_t)pw[1] * HID);

    if (val[0]) { a0 = xr0[lane]; a1 = xr0[lane + 32];
                  q0 = pr0[lane]; q1 = pr0[lane + 32]; }
    else        { a0 = a1 = q0 = q1 = z; }
    if (val[1]) { c0 = xr1[lane]; c1 = xr1[lane + 32];
                  r0 = pr1[lane]; r1 = pr1[lane + 32]; }
    else        { c0 = c1 = r0 = r1 = z; }

    __stcs(dst_o[0] + lane,      a0);
    __stcs(dst_o[0] + lane + 32, a1);
    __stcs(dst_p[0] + lane,      q0);
    __stcs(dst_p[0] + lane + 32, q1);
    __stcs(dst_o[1] + lane,      c0);
    __stcs(dst_o[1] + lane + 32, c1);
    __stcs(dst_p[1] + lane,      r0);
    __stcs(dst_p[1] + lane + 32, r1);
}

extern "C" void kernel_launch(void* const* d_in, const int* in_sizes, int n_in,
                              void* d_out, int out_size) {
    const float* x    = (const float*)d_in[0];   // (64,160,256) f32
    const float* penc = (const float*)d_in[1];   // (2001,256) f32
    const int*   dur  = (const int*)d_in[2];     // (64,160) int32
    // d_in[3] (max_len scalar) unused — fixed at 2000

    float* out = (float*)d_out;                                   // (64,2000,256)
    float* pos = out + (size_t)BATCH * MAXLEN * HID;              // (64,2000,256)
    float* mel = out + 2 * (size_t)BATCH * MAXLEN * HID;          // (64,)

    dim3 grid(MAXLEN / 16, BATCH);
    lr_fused_kernel<<<grid, 256>>>(x, penc, dur, out, pos, mel);
}